// round 8
// baseline (speedup 1.0000x reference)
#include <cuda_runtime.h>
#include <cuda_fp16.h>
#include <math.h>
#include <stdint.h>

// ---- smem byte offsets (per 64-row CTA) ----
#define A_OFF  0                 // [64][184] fp16 (k 0..175 used), row stride 368B
#define WBUF   23552             // 2 x 23552 : W1 chunks [64n][184k]
#define VBUF   70656             // 2 x 16896 : W2 chunks [32n][264k]
#define BIAS0  104448
#define BIAS1  105472
#define L2WS   106496
#define SMEMSZ 107520

__device__ float g_base[128 * 512];
__device__ __align__(16) __half g_W1[512 * 176];   // n-major: [hs 0..127 | sp 128..159 | pos 160..175]
__device__ __align__(16) __half g_W2[256 * 256];   // n-major

// ---------------- helpers ----------------
__device__ __forceinline__ uint32_t smem_u32(const void* p) {
    uint32_t a;
    asm("{ .reg .u64 t; cvta.to.shared.u64 t, %1; cvt.u32.u64 %0, t; }" : "=r"(a) : "l"(p));
    return a;
}
#define CP16(dst, src) asm volatile("cp.async.cg.shared.global [%0], [%1], 16;" :: "r"(dst), "l"(src))
#define CPCOMMIT()     asm volatile("cp.async.commit_group;")
#define CPWAIT(n)      asm volatile("cp.async.wait_group %0;" :: "n"(n))

__device__ __forceinline__ void ldsm4(uint32_t& r0, uint32_t& r1, uint32_t& r2, uint32_t& r3, uint32_t a) {
    asm volatile("ldmatrix.sync.aligned.m8n8.x4.shared.b16 {%0,%1,%2,%3}, [%4];"
                 : "=r"(r0), "=r"(r1), "=r"(r2), "=r"(r3) : "r"(a));
}
#define MMA(c, A0, A1, A2, A3, B0, B1)                                      \
    asm volatile("mma.sync.aligned.m16n8k16.row.col.f32.f16.f16.f32 "       \
                 "{%0,%1,%2,%3}, {%4,%5,%6,%7}, {%8,%9}, {%0,%1,%2,%3};"    \
                 : "+f"((c)[0]), "+f"((c)[1]), "+f"((c)[2]), "+f"((c)[3])   \
                 : "r"(A0), "r"(A1), "r"(A2), "r"(A3), "r"(B0), "r"(B1))

// issue-only (caller commits)
__device__ __forceinline__ void loadW1(uint32_t sb, int ci, int slot, int tid) {
    const char* src = (const char*)g_W1 + (size_t)ci * 64 * 352;
    uint32_t dst = sb + WBUF + slot * 23552;
#pragma unroll
    for (int j = 0; j < 11; j++) {                 // 1408 = 128*11 exact
        int idx = tid + j * 128;
        int row = idx / 22, seg = idx % 22;
        CP16(dst + row * 368 + seg * 16, src + row * 352 + seg * 16);
    }
}
__device__ __forceinline__ void loadV(uint32_t sb, int nc, int slot, int tid) {
    const char* src = (const char*)g_W2 + (size_t)nc * 32 * 512;
    uint32_t dst = sb + VBUF + slot * 16896;
#pragma unroll
    for (int j = 0; j < 8; j++) {                  // 1024 = 128*8 exact
        int idx = tid + j * 128;
        int row = idx >> 5, seg = idx & 31;
        CP16(dst + row * 528 + seg * 16, src + row * 512 + seg * 16);
    }
}

template <int KT>
__device__ __forceinline__ void g1_consume(float acc[8][4], const uint32_t aF[11][4], uint32_t wb) {
#pragma unroll
    for (int k = 0; k < KT; k++) {
#pragma unroll
        for (int s2 = 0; s2 < 4; s2++) {
            uint32_t b0, b1, b2, b3;
            ldsm4(b0, b1, b2, b3, wb + s2 * (16 * 368) + k * 32);
            MMA(acc[2 * s2],     aF[k][0], aF[k][1], aF[k][2], aF[k][3], b0, b1);
            MMA(acc[2 * s2 + 1], aF[k][0], aF[k][1], aF[k][2], aF[k][3], b2, b3);
        }
    }
}
__device__ __forceinline__ void g2_half(float (*acc)[4], const uint32_t xF[16][4], uint32_t vb) {
#pragma unroll
    for (int k = 0; k < 16; k++) {
#pragma unroll
        for (int s2 = 0; s2 < 2; s2++) {
            uint32_t b0, b1, b2, b3;
            ldsm4(b0, b1, b2, b3, vb + s2 * (16 * 528) + k * 32);
            MMA(acc[2 * s2],     xF[k][0], xF[k][1], xF[k][2], xF[k][3], b0, b1);
            MMA(acc[2 * s2 + 1], xF[k][0], xF[k][1], xF[k][2], xF[k][3], b2, b3);
        }
    }
}

// ---------------- prep kernels ----------------
__global__ void base_kernel(const float* __restrict__ code, const int* __restrict__ dir_idx,
                            const float* __restrict__ dir_emb, const float* __restrict__ ltm_w,
                            const float* __restrict__ ltm_b) {
    int b = blockIdx.x, j = threadIdx.x;
    float acc = ltm_b[j];
    const float* c = code + b * 128;
#pragma unroll 4
    for (int k = 0; k < 128; k++) acc = fmaf(c[k], ltm_w[k * 512 + j], acc);
    const float* dv = dir_emb + dir_idx[b] * 8;
#pragma unroll
    for (int k = 0; k < 8; k++) acc = fmaf(dv[k], ltm_w[(288 + k) * 512 + j], acc);
    g_base[b * 512 + j] = acc;
}

__global__ void prepW1(const float* __restrict__ ltm_w, const float* __restrict__ l0_w) {
    int idx = blockIdx.x * 256 + threadIdx.x;         // 512*176 = 90112
    if (idx >= 512 * 176) return;
    int n = idx / 176, k = idx % 176;
    float v;
    if (k < 160) v = ltm_w[(128 + k) * 512 + n];
    else         v = (n < 256) ? l0_w[(k - 160) * 256 + n] : 0.0f;
    g_W1[idx] = __float2half_rn(v);
}

__global__ void prepW2(const float* __restrict__ l1_w) {
    int idx = blockIdx.x * 256 + threadIdx.x;         // 65536
    int n = idx >> 8, k = idx & 255;
    g_W2[idx] = __float2half_rn(l1_w[k * 256 + n]);
}

// ---------------- main fused kernel ----------------
__global__ __launch_bounds__(128, 2) void main_kernel(
    const float* __restrict__ coords, const float* __restrict__ hs,
    const float* __restrict__ xstat,
    const float* __restrict__ se_w1, const float* __restrict__ se_b1,
    const float* __restrict__ se_w2, const float* __restrict__ se_b2,
    const float* __restrict__ l0_b, const float* __restrict__ l1_b,
    const float* __restrict__ l2_w, const float* __restrict__ l2_b,
    float* __restrict__ out)
{
    extern __shared__ char sh[];
    uint32_t sb = smem_u32(sh);
    const int tid = threadIdx.x, wid = tid >> 5, L = tid & 31;
    const int b = blockIdx.x >> 4, t0 = (blockIdx.x & 15) << 6;
    const int m0 = wid * 16;

    // G0, G1: first two W1 chunks
    loadW1(sb, 0, 0, tid); CPCOMMIT();
    loadW1(sb, 1, 1, tid); CPCOMMIT();

    // ---- stage A (single fp16, 64 rows) ----
    {   // hs -> k 0..127
        const float4* hs4 = (const float4*)(hs + ((size_t)(b * 1024 + t0)) * 128);
#pragma unroll
        for (int i = 0; i < 16; i++) {
            int idx = tid + i * 128;
            int r = idx >> 5, q = idx & 31;
            float4 v = hs4[r * 32 + q];
            __half2* dst = (__half2*)(sh + A_OFF + r * 368 + q * 8);
            dst[0] = __halves2half2(__float2half_rn(v.x), __float2half_rn(v.y));
            dst[1] = __halves2half2(__float2half_rn(v.z), __float2half_rn(v.w));
        }
    }
    {   // pos -> k 160..175 (sin at 160+p, cos at 168+p)
        const float* crd = coords + (size_t)b * 1024 + t0;
#pragma unroll
        for (int i = 0; i < 4; i++) {
            int idx = tid + i * 128;                  // 0..511
            int r = idx >> 3, p = idx & 7;
            float ang = crd[r] * (1.25f * (float)p);
            char* base = sh + A_OFF + r * 368;
            *(__half*)(base + (160 + p) * 2) = __float2half_rn(sinf(ang));
            *(__half*)(base + (168 + p) * 2) = __float2half_rn(cosf(ang));
        }
    }
    {   // spatial (gelu MLP) -> k 128..159 ; two threads per time row
        int r = tid >> 1, hf = tid & 1;
        float4 xs = *(const float4*)(xstat + ((size_t)(b * 1024 + t0 + r)) * 4);
        float h[16];
#pragma unroll
        for (int c = 0; c < 16; c++) {
            int ci = hf * 16 + c;
            float a = se_b1[ci];
            a = fmaf(xs.x, se_w1[ci], a);       a = fmaf(xs.y, se_w1[32 + ci], a);
            a = fmaf(xs.z, se_w1[64 + ci], a);  a = fmaf(xs.w, se_w1[96 + ci], a);
            h[c] = 0.5f * a * (1.0f + erff(a * 0.7071067811865476f));
        }
#pragma unroll
        for (int k2 = 0; k2 < 32; k2++) {
            float pp = hf ? 0.0f : se_b2[k2];
#pragma unroll
            for (int c = 0; c < 16; c++) pp = fmaf(h[c], se_w2[(hf * 16 + c) * 32 + k2], pp);
            pp += __shfl_xor_sync(0xffffffffu, pp, 1);
            if ((k2 >> 4) == hf)
                *(__half*)(sh + A_OFF + r * 368 + (128 + k2) * 2) = __float2half_rn(pp);
        }
    }
    {   // biases + l2 weights (256 floats each, 2 iters at 128 threads)
        float* b0s = (float*)(sh + BIAS0);
        float* b1s = (float*)(sh + BIAS1);
        float* lws = (float*)(sh + L2WS);
        b0s[tid]       = g_base[b * 512 + tid]       + l0_b[tid];
        b0s[tid + 128] = g_base[b * 512 + tid + 128] + l0_b[tid + 128];
        b1s[tid]       = g_base[b * 512 + 256 + tid] + l1_b[tid];
        b1s[tid + 128] = g_base[b * 512 + 384 + tid] + l1_b[tid + 128];
        lws[tid]       = l2_w[tid];
        lws[tid + 128] = l2_w[tid + 128];
    }

    // fragment addressing
    const uint32_t aRow  = m0 + (L & 15);
    const uint32_t aColB = (L >> 4) * 16;
    const uint32_t aAddr = sb + A_OFF + aRow * 368 + aColB;
    const uint32_t bRowL = (L & 7) + ((L >> 4) << 3);
    const uint32_t bColB = ((L >> 3) & 1) * 16;
    const uint32_t w1Base = bRowL * 368 + bColB;
    const uint32_t w2Base = bRowL * 528 + bColB;
    const float* bias0 = (const float*)(sh + BIAS0);
    const float* bias1 = (const float*)(sh + BIAS1);
    const float* lw    = (const float*)(sh + L2WS);
    const int colL = 2 * (L & 3);

    uint32_t aF[11][4];    // A fragments, reused by all 8 W1 chunks
    uint32_t xF[16][4];    // x0 fragments, built from G1 accumulators

    // ---- phase 1: G1 chunks 0..3 -> x0 into registers ----
#pragma unroll
    for (int ci = 0; ci < 4; ci++) {
        CPWAIT(1);
        __syncthreads();
        if (ci == 0) {
#pragma unroll
            for (int k = 0; k < 11; k++) ldsm4(aF[k][0], aF[k][1], aF[k][2], aF[k][3], aAddr + k * 32);
        }
        float acc[8][4];
#pragma unroll
        for (int s = 0; s < 8; s++) {
            float b0v = bias0[ci * 64 + s * 8 + colL];
            float b1v = bias0[ci * 64 + s * 8 + colL + 1];
            acc[s][0] = b0v; acc[s][1] = b1v; acc[s][2] = b0v; acc[s][3] = b1v;
        }
        g1_consume<11>(acc, aF, sb + WBUF + (uint32_t)(ci & 1) * 23552 + w1Base);
#pragma unroll
        for (int t = 0; t < 4; t++) {
            __half2 p0 = __floats2half2_rn(fmaxf(acc[2*t][0],   0.f), fmaxf(acc[2*t][1],   0.f));
            __half2 p1 = __floats2half2_rn(fmaxf(acc[2*t][2],   0.f), fmaxf(acc[2*t][3],   0.f));
            __half2 p2 = __floats2half2_rn(fmaxf(acc[2*t+1][0], 0.f), fmaxf(acc[2*t+1][1], 0.f));
            __half2 p3 = __floats2half2_rn(fmaxf(acc[2*t+1][2], 0.f), fmaxf(acc[2*t+1][3], 0.f));
            xF[4*ci + t][0] = reinterpret_cast<uint32_t&>(p0);
            xF[4*ci + t][1] = reinterpret_cast<uint32_t&>(p1);
            xF[4*ci + t][2] = reinterpret_cast<uint32_t&>(p2);
            xF[4*ci + t][3] = reinterpret_cast<uint32_t&>(p3);
        }
        __syncthreads();   // all warps done with W1 slot (ci&1)
        if (ci == 0) { loadW1(sb, 2, 0, tid); CPCOMMIT(); }                                    // G2
        if (ci == 1) { loadW1(sb, 3, 1, tid); CPCOMMIT(); }                                    // G3
        if (ci == 2) { loadW1(sb, 4, 0, tid); CPCOMMIT(); }                                    // G4
        if (ci == 3) { loadW1(sb, 5, 1, tid); loadV(sb, 0, 0, tid); loadV(sb, 1, 1, tid); CPCOMMIT(); }  // G5
    }

    // ---- phase 2: per 64-col group m: mods1 (W1 c4+m) + G2 (two 32n V chunks) + reduce ----
    float s0 = 0.0f, s1 = 0.0f;
#pragma unroll
    for (int m = 0; m < 4; m++) {
        if (m == 0) { CPWAIT(1); __syncthreads(); }   // G4 (c4) done; G5 may pend
        float acc[8][4];
#pragma unroll
        for (int s = 0; s < 8; s++) {
            float b0v = bias1[m * 64 + s * 8 + colL];
            float b1v = bias1[m * 64 + s * 8 + colL + 1];
            acc[s][0] = b0v; acc[s][1] = b1v; acc[s][2] = b0v; acc[s][3] = b1v;
        }
        // mods1 contribution (skip all-zero pos k-tile: 10 k-tiles)
        g1_consume<10>(acc, aF, sb + WBUF + (uint32_t)(m & 1) * 23552 + w1Base);
        // wait for this m's V pair (+ next W1 chunk, bundled in same group)
        CPWAIT(0);
        __syncthreads();
        g2_half(acc,     xF, sb + VBUF + w2Base);
        g2_half(acc + 4, xF, sb + VBUF + 16896 + w2Base);
        __syncthreads();   // all warps done with both V slots and W1 slot (m&1)
        if (m == 0) { loadW1(sb, 6, 0, tid); loadV(sb, 2, 0, tid); loadV(sb, 3, 1, tid); CPCOMMIT(); } // G6
        if (m == 1) { loadW1(sb, 7, 1, tid); loadV(sb, 4, 0, tid); loadV(sb, 5, 1, tid); CPCOMMIT(); } // G7
        if (m == 2) {                        loadV(sb, 6, 0, tid); loadV(sb, 7, 1, tid); CPCOMMIT(); } // G8
        // relu + dot with l2_w
#pragma unroll
        for (int s = 0; s < 8; s++) {
            int c = m * 64 + s * 8 + colL;
            float w0 = lw[c], w1 = lw[c + 1];
            s0 += fmaxf(acc[s][0], 0.0f) * w0 + fmaxf(acc[s][1], 0.0f) * w1;
            s1 += fmaxf(acc[s][2], 0.0f) * w0 + fmaxf(acc[s][3], 0.0f) * w1;
        }
    }

    // ---- final reduce + store ----
    s0 += __shfl_xor_sync(0xffffffffu, s0, 1);  s0 += __shfl_xor_sync(0xffffffffu, s0, 2);
    s1 += __shfl_xor_sync(0xffffffffu, s1, 1);  s1 += __shfl_xor_sync(0xffffffffu, s1, 2);
    if ((L & 3) == 0) {
        float lb = l2_b[0];
        int r0 = m0 + (L >> 2);
        out[(size_t)b * 1024 + t0 + r0]     = s0 + lb;
        out[(size_t)b * 1024 + t0 + r0 + 8] = s1 + lb;
    }
}

extern "C" void kernel_launch(void* const* d_in, const int* in_sizes, int n_in,
                              void* d_out, int out_size) {
    const float* coords  = (const float*)d_in[0];
    const float* code    = (const float*)d_in[1];
    const float* hs      = (const float*)d_in[2];
    const float* xstat   = (const float*)d_in[3];
    const int*   dir_idx = (const int*)  d_in[4];
    const float* se_w1   = (const float*)d_in[5];
    const float* se_b1   = (const float*)d_in[6];
    const float* se_w2   = (const float*)d_in[7];
    const float* se_b2   = (const float*)d_in[8];
    const float* dir_emb = (const float*)d_in[9];
    const float* ltm_w   = (const float*)d_in[10];
    const float* ltm_b   = (const float*)d_in[11];
    const float* l0_w    = (const float*)d_in[12];
    const float* l0_b    = (const float*)d_in[13];
    const float* l1_w    = (const float*)d_in[14];
    const float* l1_b    = (const float*)d_in[15];
    const float* l2_w    = (const float*)d_in[16];
    const float* l2_b    = (const float*)d_in[17];
    float* out = (float*)d_out;

    cudaFuncSetAttribute(main_kernel, cudaFuncAttributeMaxDynamicSharedMemorySize, SMEMSZ);

    base_kernel<<<128, 512>>>(code, dir_idx, dir_emb, ltm_w, ltm_b);
    prepW1<<<353, 256>>>(ltm_w, l0_w);
    prepW2<<<256, 256>>>(l1_w);
    main_kernel<<<2048, 128, SMEMSZ>>>(coords, hs, xstat, se_w1, se_b1, se_w2, se_b2,
                                       l0_b, l1_b, l2_w, l2_b, out);
}

// round 9
// speedup vs baseline: 1.0902x; 1.0902x over previous
#include <cuda_runtime.h>
#include <cuda_fp16.h>
#include <math.h>
#include <stdint.h>

// ---- smem byte offsets (128-row CTA, 1 CTA/SM) ----
#define A_OFF  0                 // [128][184] fp16 (k 0..175 used), row stride 368B
#define WBUF   47104             // 4 x 23552 : W1 chunks [64n][184k]
#define VBUF   141312            // 4 x 16896 : W2 chunks [32n][264k]; also hs scratch (64KB) at start
#define BIAS0  208896
#define BIAS1  209920
#define L2WS   210944
#define SMEMSZ 211968

__device__ float g_base[128 * 512];
__device__ __align__(16) __half g_W1[512 * 176];   // n-major: [hs 0..127 | sp 128..159 | pos 160..175]
__device__ __align__(16) __half g_W2[256 * 256];   // n-major

// ---------------- helpers ----------------
__device__ __forceinline__ uint32_t smem_u32(const void* p) {
    uint32_t a;
    asm("{ .reg .u64 t; cvta.to.shared.u64 t, %1; cvt.u32.u64 %0, t; }" : "=r"(a) : "l"(p));
    return a;
}
#define CP16(dst, src) asm volatile("cp.async.cg.shared.global [%0], [%1], 16;" :: "r"(dst), "l"(src))
#define CPCOMMIT()     asm volatile("cp.async.commit_group;")
#define CPWAIT(n)      asm volatile("cp.async.wait_group %0;" :: "n"(n))

__device__ __forceinline__ void ldsm4(uint32_t& r0, uint32_t& r1, uint32_t& r2, uint32_t& r3, uint32_t a) {
    asm volatile("ldmatrix.sync.aligned.m8n8.x4.shared.b16 {%0,%1,%2,%3}, [%4];"
                 : "=r"(r0), "=r"(r1), "=r"(r2), "=r"(r3) : "r"(a));
}
#define MMA(c, A0, A1, A2, A3, B0, B1)                                      \
    asm volatile("mma.sync.aligned.m16n8k16.row.col.f32.f16.f16.f32 "       \
                 "{%0,%1,%2,%3}, {%4,%5,%6,%7}, {%8,%9}, {%0,%1,%2,%3};"    \
                 : "+f"((c)[0]), "+f"((c)[1]), "+f"((c)[2]), "+f"((c)[3])   \
                 : "r"(A0), "r"(A1), "r"(A2), "r"(A3), "r"(B0), "r"(B1))

// issue-only (caller commits)
__device__ __forceinline__ void loadW1(uint32_t sb, int ci, int slot, int tid) {
    const char* src = (const char*)g_W1 + (size_t)ci * 64 * 352;
    uint32_t dst = sb + WBUF + slot * 23552;
#pragma unroll
    for (int j = 0; j < 6; j++) {
        int idx = tid + j * 256;
        if (idx < 1408) {
            int row = idx / 22, seg = idx % 22;
            CP16(dst + row * 368 + seg * 16, src + row * 352 + seg * 16);
        }
    }
}
__device__ __forceinline__ void loadV(uint32_t sb, int nc, int slot, int tid) {
    const char* src = (const char*)g_W2 + (size_t)nc * 32 * 512;
    uint32_t dst = sb + VBUF + slot * 16896;
#pragma unroll
    for (int j = 0; j < 4; j++) {                  // 1024 = 256*4 exact
        int idx = tid + j * 256;
        int row = idx >> 5, seg = idx & 31;
        CP16(dst + row * 528 + seg * 16, src + row * 512 + seg * 16);
    }
}

template <int KT>
__device__ __forceinline__ void g1_consume(float acc[8][4], const uint32_t aF[11][4], uint32_t wb) {
#pragma unroll
    for (int k = 0; k < KT; k++) {
#pragma unroll
        for (int s2 = 0; s2 < 4; s2++) {
            uint32_t b0, b1, b2, b3;
            ldsm4(b0, b1, b2, b3, wb + s2 * (16 * 368) + k * 32);
            MMA(acc[2 * s2],     aF[k][0], aF[k][1], aF[k][2], aF[k][3], b0, b1);
            MMA(acc[2 * s2 + 1], aF[k][0], aF[k][1], aF[k][2], aF[k][3], b2, b3);
        }
    }
}
__device__ __forceinline__ void g2_half(float (*acc)[4], const uint32_t xF[16][4], uint32_t vb) {
#pragma unroll
    for (int k = 0; k < 16; k++) {
#pragma unroll
        for (int s2 = 0; s2 < 2; s2++) {
            uint32_t b0, b1, b2, b3;
            ldsm4(b0, b1, b2, b3, vb + s2 * (16 * 528) + k * 32);
            MMA(acc[2 * s2],     xF[k][0], xF[k][1], xF[k][2], xF[k][3], b0, b1);
            MMA(acc[2 * s2 + 1], xF[k][0], xF[k][1], xF[k][2], xF[k][3], b2, b3);
        }
    }
}

// ---------------- prep kernels ----------------
__global__ void base_kernel(const float* __restrict__ code, const int* __restrict__ dir_idx,
                            const float* __restrict__ dir_emb, const float* __restrict__ ltm_w,
                            const float* __restrict__ ltm_b) {
    int b = blockIdx.x, j = threadIdx.x;
    float acc = ltm_b[j];
    const float* c = code + b * 128;
#pragma unroll 4
    for (int k = 0; k < 128; k++) acc = fmaf(c[k], ltm_w[k * 512 + j], acc);
    const float* dv = dir_emb + dir_idx[b] * 8;
#pragma unroll
    for (int k = 0; k < 8; k++) acc = fmaf(dv[k], ltm_w[(288 + k) * 512 + j], acc);
    g_base[b * 512 + j] = acc;
}

__global__ void prepW1(const float* __restrict__ ltm_w, const float* __restrict__ l0_w) {
    int idx = blockIdx.x * 256 + threadIdx.x;         // 512*176 = 90112
    if (idx >= 512 * 176) return;
    int n = idx / 176, k = idx % 176;
    float v;
    if (k < 160) v = ltm_w[(128 + k) * 512 + n];
    else         v = (n < 256) ? l0_w[(k - 160) * 256 + n] : 0.0f;
    g_W1[idx] = __float2half_rn(v);
}

__global__ void prepW2(const float* __restrict__ l1_w) {
    int idx = blockIdx.x * 256 + threadIdx.x;         // 65536
    int n = idx >> 8, k = idx & 255;
    g_W2[idx] = __float2half_rn(l1_w[k * 256 + n]);
}

// ---------------- main fused kernel ----------------
__global__ __launch_bounds__(256, 1) void main_kernel(
    const float* __restrict__ coords, const float* __restrict__ hs,
    const float* __restrict__ xstat,
    const float* __restrict__ se_w1, const float* __restrict__ se_b1,
    const float* __restrict__ se_w2, const float* __restrict__ se_b2,
    const float* __restrict__ l0_b, const float* __restrict__ l1_b,
    const float* __restrict__ l2_w, const float* __restrict__ l2_b,
    float* __restrict__ out)
{
    extern __shared__ char sh[];
    uint32_t sb = smem_u32(sh);
    const int tid = threadIdx.x, wid = tid >> 5, L = tid & 31;
    const int b = blockIdx.x >> 3, t0 = (blockIdx.x & 7) << 7;
    const int m0 = wid * 16;

    // ---- g0: hs burst into VBUF scratch (64KB contiguous) ----
    {
        const char* hsrc = (const char*)(hs + ((size_t)(b * 1024 + t0)) * 128);
#pragma unroll
        for (int j = 0; j < 16; j++) {
            int idx = tid + j * 256;                  // 0..4095
            CP16(sb + VBUF + idx * 16, hsrc + idx * 16);
        }
        CPCOMMIT();
    }
    // ---- g1..g4: W1 c0..c3 into slots 0..3 ----
    loadW1(sb, 0, 0, tid); CPCOMMIT();
    loadW1(sb, 1, 1, tid); CPCOMMIT();
    loadW1(sb, 2, 2, tid); CPCOMMIT();
    loadW1(sb, 3, 3, tid); CPCOMMIT();

    // ---- LDG prefetch (latency hidden under hs burst) ----
    float4 xs = *(const float4*)(xstat + ((size_t)(b * 1024 + t0 + (tid >> 1))) * 4);
    float cc[4];
#pragma unroll
    for (int i = 0; i < 4; i++) cc[i] = coords[(size_t)b * 1024 + t0 + ((tid + i * 256) >> 3)];
    float gb0 = g_base[b * 512 + tid],      gb1 = g_base[b * 512 + 256 + tid];
    float lb0 = l0_b[tid], lb1 = l1_b[tid], lwv = l2_w[tid];

    CPWAIT(4);          // g0 (hs) retired; W1 groups may pend
    __syncthreads();    // hs visible to all threads

    // ---- stage A (single fp16) ----
    {   // hs convert: VBUF scratch -> A (k 0..127)
#pragma unroll
        for (int i = 0; i < 16; i++) {
            int idx = tid + i * 256;
            int r = idx >> 5, q = idx & 31;
            float4 v = *(const float4*)(sh + VBUF + r * 512 + q * 16);
            __half2* dst = (__half2*)(sh + A_OFF + r * 368 + q * 8);
            dst[0] = __halves2half2(__float2half_rn(v.x), __float2half_rn(v.y));
            dst[1] = __halves2half2(__float2half_rn(v.z), __float2half_rn(v.w));
        }
    }
    {   // pos -> k 160..175 (sin at 160+p, cos at 168+p)
#pragma unroll
        for (int i = 0; i < 4; i++) {
            int idx = tid + i * 256;                  // 0..1023
            int r = idx >> 3, p = idx & 7;
            float ang = cc[i] * (1.25f * (float)p);
            char* base = sh + A_OFF + r * 368;
            *(__half*)(base + (160 + p) * 2) = __float2half_rn(sinf(ang));
            *(__half*)(base + (168 + p) * 2) = __float2half_rn(cosf(ang));
        }
    }
    {   // spatial (gelu MLP) -> k 128..159 ; two threads per time row
        int r = tid >> 1, hf = tid & 1;
        float h[16];
#pragma unroll
        for (int c = 0; c < 16; c++) {
            int ci = hf * 16 + c;
            float a = se_b1[ci];
            a = fmaf(xs.x, se_w1[ci], a);       a = fmaf(xs.y, se_w1[32 + ci], a);
            a = fmaf(xs.z, se_w1[64 + ci], a);  a = fmaf(xs.w, se_w1[96 + ci], a);
            h[c] = 0.5f * a * (1.0f + erff(a * 0.7071067811865476f));
        }
#pragma unroll
        for (int k2 = 0; k2 < 32; k2++) {
            float pp = hf ? 0.0f : se_b2[k2];
#pragma unroll
            for (int c = 0; c < 16; c++) pp = fmaf(h[c], se_w2[(hf * 16 + c) * 32 + k2], pp);
            pp += __shfl_xor_sync(0xffffffffu, pp, 1);
            if ((k2 >> 4) == hf)
                *(__half*)(sh + A_OFF + r * 368 + (128 + k2) * 2) = __float2half_rn(pp);
        }
    }
    ((float*)(sh + BIAS0))[tid] = gb0 + lb0;
    ((float*)(sh + BIAS1))[tid] = gb1 + lb1;
    ((float*)(sh + L2WS))[tid]  = lwv;
    __syncthreads();    // A/bias staged; VBUF scratch free

    // ---- g5, g6: V0, V1 into V slots 0, 1 ----
    loadV(sb, 0, 0, tid); CPCOMMIT();
    loadV(sb, 1, 1, tid); CPCOMMIT();

    // fragment addressing
    const uint32_t aRow  = m0 + (L & 15);
    const uint32_t aColB = (L >> 4) * 16;
    const uint32_t aAddr = sb + A_OFF + aRow * 368 + aColB;
    const uint32_t bRowL = (L & 7) + ((L >> 4) << 3);
    const uint32_t bColB = ((L >> 3) & 1) * 16;
    const uint32_t w1Base = bRowL * 368 + bColB;
    const uint32_t w2Base = bRowL * 528 + bColB;
    const float* bias0 = (const float*)(sh + BIAS0);
    const float* bias1 = (const float*)(sh + BIAS1);
    const float* lw    = (const float*)(sh + L2WS);
    const int colL = 2 * (L & 3);

    uint32_t aF[11][4];
    uint32_t xF[16][4];

    // ---- phase 1: c0..c3 back-to-back, NO internal syncs ----
    CPWAIT(2);          // g1..g4 (W1 c0-3) retired; V0/V1 may pend
    __syncthreads();
#pragma unroll
    for (int k = 0; k < 11; k++) ldsm4(aF[k][0], aF[k][1], aF[k][2], aF[k][3], aAddr + k * 32);
#pragma unroll
    for (int ci = 0; ci < 4; ci++) {
        float acc[8][4];
#pragma unroll
        for (int s = 0; s < 8; s++) {
            float b0v = bias0[ci * 64 + s * 8 + colL];
            float b1v = bias0[ci * 64 + s * 8 + colL + 1];
            acc[s][0] = b0v; acc[s][1] = b1v; acc[s][2] = b0v; acc[s][3] = b1v;
        }
        g1_consume<11>(acc, aF, sb + WBUF + (uint32_t)ci * 23552 + w1Base);
#pragma unroll
        for (int t = 0; t < 4; t++) {
            __half2 p0 = __floats2half2_rn(fmaxf(acc[2*t][0],   0.f), fmaxf(acc[2*t][1],   0.f));
            __half2 p1 = __floats2half2_rn(fmaxf(acc[2*t][2],   0.f), fmaxf(acc[2*t][3],   0.f));
            __half2 p2 = __floats2half2_rn(fmaxf(acc[2*t+1][0], 0.f), fmaxf(acc[2*t+1][1], 0.f));
            __half2 p3 = __floats2half2_rn(fmaxf(acc[2*t+1][2], 0.f), fmaxf(acc[2*t+1][3], 0.f));
            xF[4*ci + t][0] = reinterpret_cast<uint32_t&>(p0);
            xF[4*ci + t][1] = reinterpret_cast<uint32_t&>(p1);
            xF[4*ci + t][2] = reinterpret_cast<uint32_t&>(p2);
            xF[4*ci + t][3] = reinterpret_cast<uint32_t&>(p3);
        }
    }
    __syncthreads();    // all warps done with all W1 slots

    // ---- g7..g10: W1 c4..c7 -> slots 0..3 ; g11,g12: V2,V3 -> slots 2,3 ----
    loadW1(sb, 4, 0, tid); CPCOMMIT();
    loadW1(sb, 5, 1, tid); CPCOMMIT();
    loadW1(sb, 6, 2, tid); CPCOMMIT();
    loadW1(sb, 7, 3, tid); CPCOMMIT();
    loadV (sb, 2, 2, tid); CPCOMMIT();
    loadV (sb, 3, 3, tid); CPCOMMIT();

    // ---- phase 2: per 64-col group m ----
    float s0 = 0.0f, s1 = 0.0f;
#pragma unroll
    for (int m = 0; m < 4; m++) {
        if      (m == 0) { CPWAIT(5); }   // g5,g6 (V0,V1) + g7 (c4) retired
        else if (m == 1) { CPWAIT(2); }   // g8..g12 retired (c5, V2, V3)
        else if (m == 2) { CPWAIT(2); }   // g13,g14 (V4,V5) retired
        else             { CPWAIT(0); }   // g15,g16 (V6,V7) retired
        __syncthreads();
        float acc[8][4];
#pragma unroll
        for (int s = 0; s < 8; s++) {
            float b0v = bias1[m * 64 + s * 8 + colL];
            float b1v = bias1[m * 64 + s * 8 + colL + 1];
            acc[s][0] = b0v; acc[s][1] = b1v; acc[s][2] = b0v; acc[s][3] = b1v;
        }
        // mods1 (skip all-zero pos k-tile)
        g1_consume<10>(acc, aF, sb + WBUF + (uint32_t)m * 23552 + w1Base);
        // G2: V pair in slots (2*(m&1), 2*(m&1)+1)
        uint32_t vb = sb + VBUF + (uint32_t)(m & 1) * 33792 + w2Base;
        g2_half(acc,     xF, vb);
        g2_half(acc + 4, xF, vb + 16896);
        if (m == 0) {   // refill V slots 0,1 with V4,V5 (g13,g14)
            __syncthreads();
            loadV(sb, 4, 0, tid); CPCOMMIT();
            loadV(sb, 5, 1, tid); CPCOMMIT();
        }
        if (m == 1) {   // refill V slots 2,3 with V6,V7 (g15,g16)
            __syncthreads();
            loadV(sb, 6, 2, tid); CPCOMMIT();
            loadV(sb, 7, 3, tid); CPCOMMIT();
        }
        // relu + dot with l2_w
#pragma unroll
        for (int s = 0; s < 8; s++) {
            int c = m * 64 + s * 8 + colL;
            float w0 = lw[c], w1 = lw[c + 1];
            s0 += fmaxf(acc[s][0], 0.0f) * w0 + fmaxf(acc[s][1], 0.0f) * w1;
            s1 += fmaxf(acc[s][2], 0.0f) * w0 + fmaxf(acc[s][3], 0.0f) * w1;
        }
    }

    // ---- final reduce + store ----
    s0 += __shfl_xor_sync(0xffffffffu, s0, 1);  s0 += __shfl_xor_sync(0xffffffffu, s0, 2);
    s1 += __shfl_xor_sync(0xffffffffu, s1, 1);  s1 += __shfl_xor_sync(0xffffffffu, s1, 2);
    if ((L & 3) == 0) {
        float lb = l2_b[0];
        int r0 = m0 + (L >> 2);
        out[(size_t)b * 1024 + t0 + r0]     = s0 + lb;
        out[(size_t)b * 1024 + t0 + r0 + 8] = s1 + lb;
    }
}

extern "C" void kernel_launch(void* const* d_in, const int* in_sizes, int n_in,
                              void* d_out, int out_size) {
    const float* coords  = (const float*)d_in[0];
    const float* code    = (const float*)d_in[1];
    const float* hs      = (const float*)d_in[2];
    const float* xstat   = (const float*)d_in[3];
    const int*   dir_idx = (const int*)  d_in[4];
    const float* se_w1   = (const float*)d_in[5];
    const float* se_b1   = (const float*)d_in[6];
    const float* se_w2   = (const float*)d_in[7];
    const float* se_b2   = (const float*)d_in[8];
    const float* dir_emb = (const float*)d_in[9];
    const float* ltm_w   = (const float*)d_in[10];
    const float* ltm_b   = (const float*)d_in[11];
    const float* l0_w    = (const float*)d_in[12];
    const float* l0_b    = (const float*)d_in[13];
    const float* l1_w    = (const float*)d_in[14];
    const float* l1_b    = (const float*)d_in[15];
    const float* l2_w    = (const float*)d_in[16];
    const float* l2_b    = (const float*)d_in[17];
    float* out = (float*)d_out;

    cudaFuncSetAttribute(main_kernel, cudaFuncAttributeMaxDynamicSharedMemorySize, SMEMSZ);

    base_kernel<<<128, 512>>>(code, dir_idx, dir_emb, ltm_w, ltm_b);
    prepW1<<<353, 256>>>(ltm_w, l0_w);
    prepW2<<<256, 256>>>(l1_w);
    main_kernel<<<1024, 256, SMEMSZ>>>(coords, hs, xstat, se_w1, se_b1, se_w2, se_b2,
                                       l0_b, l1_b, l2_w, l2_b, out);
}